// round 15
// baseline (speedup 1.0000x reference)
#include <cuda_runtime.h>
#include <cuda_fp16.h>

// RNNBlock: h_t = tanh(x_t @ Wx[t] + h_{t-1} @ Wh[t]), h_{-1}=0
// B=512, S=512, D=256, fp32 in/out.  Compute: fp16 m16n8k16, fp32 accumulate.
//
// K0a: pack Wx -> fp16x2 (8x32-col groups, K1 layout).
// K0b: pack Wh -> fp16x2 (16x16-col groups, K2 layout).
// K1:  Z = x @ Wx -> g_ZP (fp16, K2 per-thread accumulator order).
// K2:  recurrence, 64 CTAs (32 pairs x 2 ranks). Pair = 16 batch rows; rank r
//      owns cols [128r,128r+128). 512 threads = 2 K-halves x 8 colgroups(16c).
//      Own-K A-frags from smem; other-K A-frags from the peer CTA via a gmem
//      exchange slot (fp16 A-frag order) + release/acquire flag per step.
//      Weights: depth-4 register ring (1 LDG.128/kit/warp). Z via cp.async.

#define S_LEN 512
#define B_SZ  512
#define DIM   256
#define TM1   32
#define XSTR  132              // K1 xs row stride (u32)
#define WT4   8192             // uint4 per timestep of packed weights
#define PFD   4                // weight ring depth

__device__ uint4 g_WxP4[(size_t)S_LEN * WT4];          // 64MB, K1 layout
__device__ uint4 g_WhP16[(size_t)S_LEN * WT4];         // 64MB, K2 16-colgroup layout
__device__ uint4 g_ZP[(size_t)32 * S_LEN * 512];       // 134MB fp16 Z, thread-order
__device__ uint4 g_HX[(size_t)64 * 513 * 256];         // h exchange slots (t+1 shifted)
__device__ unsigned g_flag[64 * 513];                  // publish flags (memset / launch)

__device__ __forceinline__ unsigned pack2h(float lo, float hi) {
    __half2 h = __floats2half2_rn(lo, hi);
    return *reinterpret_cast<unsigned*>(&h);
}

__device__ __forceinline__ void mma_f16(float c[4],
                                        unsigned a0, unsigned a1, unsigned a2, unsigned a3,
                                        unsigned b0, unsigned b1) {
    asm volatile(
        "mma.sync.aligned.m16n8k16.row.col.f32.f16.f16.f32 "
        "{%0,%1,%2,%3}, {%4,%5,%6,%7}, {%8,%9}, {%0,%1,%2,%3};"
        : "+f"(c[0]), "+f"(c[1]), "+f"(c[2]), "+f"(c[3])
        : "r"(a0), "r"(a1), "r"(a2), "r"(a3), "r"(b0), "r"(b1));
}

__device__ __forceinline__ float fast_tanh(float x) {
    x = fminf(fmaxf(x, -15.f), 15.f);
    float e = __expf(2.f * x);
    return __fdividef(e - 1.f, e + 1.f);
}

__device__ __forceinline__ void cp_async16(void* dst_smem, const void* src) {
    unsigned d = (unsigned)__cvta_generic_to_shared(dst_smem);
    asm volatile("cp.async.cg.shared.global [%0], [%1], 16;" :: "r"(d), "l"(src));
}
#define CP_COMMIT() asm volatile("cp.async.commit_group;")
#define CP_WAIT1()  asm volatile("cp.async.wait_group 1;" ::: "memory")

__device__ __forceinline__ unsigned ld_acq(const unsigned* p) {
    unsigned v;
    asm volatile("ld.acquire.gpu.b32 %0, [%1];" : "=r"(v) : "l"(p) : "memory");
    return v;
}
__device__ __forceinline__ void st_rel(unsigned* p, unsigned v) {
    asm volatile("st.release.gpu.b32 [%0], %1;" :: "l"(p), "r"(v) : "memory");
}

// ---------- K0a: pack Wx (K1 8x32-col layout) -------------------------------------
// uint4 idx = t*8192 + w*1024 + kit*64 + pair*32 + lane   (w<8, kit<16, pair<2)
__global__ void __launch_bounds__(256)
pack_wx(const float* __restrict__ W, uint4* __restrict__ P) {
    unsigned idx  = blockIdx.x * 256u + threadIdx.x;
    unsigned lane = idx & 31, pair = (idx >> 5) & 1, kit = (idx >> 6) & 15,
             w    = (idx >> 10) & 7, t = idx >> 13;
    unsigned g = lane >> 2, tig = lane & 3, k0 = kit * 16;
    const float* Wt = W + (size_t)t * DIM * DIM;
    unsigned n0 = w * 32 + pair * 16 + g;
    uint4 v;
    v.x = pack2h(Wt[(k0 + 2*tig)     * DIM + n0],     Wt[(k0 + 2*tig + 1) * DIM + n0]);
    v.y = pack2h(Wt[(k0 + 2*tig + 8) * DIM + n0],     Wt[(k0 + 2*tig + 9) * DIM + n0]);
    v.z = pack2h(Wt[(k0 + 2*tig)     * DIM + n0 + 8], Wt[(k0 + 2*tig + 1) * DIM + n0 + 8]);
    v.w = pack2h(Wt[(k0 + 2*tig + 8) * DIM + n0 + 8], Wt[(k0 + 2*tig + 9) * DIM + n0 + 8]);
    P[idx] = v;
}

// ---------- K0b: pack Wh (K2 16x16-col layout) ------------------------------------
// uint4 idx = t*8192 + gw*512 + kit*32 + lane   (gw<16 colgroups of 16, kit<16)
// n0 = gw*16 + g, k0 = kit*16
__global__ void __launch_bounds__(256)
pack_wh(const float* __restrict__ W, uint4* __restrict__ P) {
    unsigned idx  = blockIdx.x * 256u + threadIdx.x;
    unsigned lane = idx & 31, kit = (idx >> 5) & 15,
             gw   = (idx >> 9) & 15, t = idx >> 13;
    unsigned g = lane >> 2, tig = lane & 3, k0 = kit * 16;
    const float* Wt = W + (size_t)t * DIM * DIM;
    unsigned n0 = gw * 16 + g;
    uint4 v;
    v.x = pack2h(Wt[(k0 + 2*tig)     * DIM + n0],     Wt[(k0 + 2*tig + 1) * DIM + n0]);
    v.y = pack2h(Wt[(k0 + 2*tig + 8) * DIM + n0],     Wt[(k0 + 2*tig + 9) * DIM + n0]);
    v.z = pack2h(Wt[(k0 + 2*tig)     * DIM + n0 + 8], Wt[(k0 + 2*tig + 1) * DIM + n0 + 8]);
    v.w = pack2h(Wt[(k0 + 2*tig + 8) * DIM + n0 + 8], Wt[(k0 + 2*tig + 9) * DIM + n0 + 8]);
    P[idx] = v;
}

// ---------- K1: Z = x @ Wx -> g_ZP (fp16, K2-thread order) -------------------------
__global__ void __launch_bounds__(256)
rnn_k1(const float* __restrict__ x, uint4* __restrict__ ZP) {
    __shared__ unsigned xs[TM1 * XSTR];
    const int bt = blockIdx.x, t = blockIdx.y, tid = threadIdx.x;
    const int w = tid >> 5, lane = tid & 31, g = lane >> 2, tig = lane & 3;
    const int b0r = bt * TM1;

    for (int i = tid; i < TM1 * (DIM / 4); i += 256) {
        int r = i >> 6, c4 = i & 63;
        float4 v = *reinterpret_cast<const float4*>(
            x + ((size_t)(b0r + r) * S_LEN + t) * DIM + c4 * 4);
        uint2 u = make_uint2(pack2h(v.x, v.y), pack2h(v.z, v.w));
        *reinterpret_cast<uint2*>(&xs[r * XSTR + c4 * 2]) = u;
    }
    __syncthreads();

    float acc[2][4][4] = {};
    const uint4* Bp = g_WxP4 + (size_t)t * WT4 + w * 1024 + lane;
#pragma unroll
    for (int kit = 0; kit < 16; kit++) {
        uint4 p0 = Bp[kit * 64];
        uint4 p1 = Bp[kit * 64 + 32];
        const int kb = kit * 8;
        unsigned a[2][4];
#pragma unroll
        for (int mi = 0; mi < 2; mi++) {
            int r0 = mi * 16 + g;
            a[mi][0] = xs[r0 * XSTR + kb + tig];
            a[mi][1] = xs[(r0 + 8) * XSTR + kb + tig];
            a[mi][2] = xs[r0 * XSTR + kb + 4 + tig];
            a[mi][3] = xs[(r0 + 8) * XSTR + kb + 4 + tig];
        }
#pragma unroll
        for (int mi = 0; mi < 2; mi++) {
            mma_f16(acc[mi][0], a[mi][0], a[mi][1], a[mi][2], a[mi][3], p0.x, p0.y);
            mma_f16(acc[mi][1], a[mi][0], a[mi][1], a[mi][2], a[mi][3], p0.z, p0.w);
            mma_f16(acc[mi][2], a[mi][0], a[mi][1], a[mi][2], a[mi][3], p1.x, p1.y);
            mma_f16(acc[mi][3], a[mi][0], a[mi][1], a[mi][2], a[mi][3], p1.z, p1.w);
        }
    }

#pragma unroll
    for (int mi = 0; mi < 2; mi++) {
        const int bt16 = 2 * bt + mi;
        uint4* dst = g_ZP + ((size_t)(bt16 * S_LEN + t) * 8 + w) * 64 + lane;
        uint4 u0, u1;
        u0.x = pack2h(acc[mi][0][0], acc[mi][0][1]);
        u0.y = pack2h(acc[mi][0][2], acc[mi][0][3]);
        u0.z = pack2h(acc[mi][1][0], acc[mi][1][1]);
        u0.w = pack2h(acc[mi][1][2], acc[mi][1][3]);
        u1.x = pack2h(acc[mi][2][0], acc[mi][2][1]);
        u1.y = pack2h(acc[mi][2][2], acc[mi][2][3]);
        u1.z = pack2h(acc[mi][3][0], acc[mi][3][1]);
        u1.w = pack2h(acc[mi][3][2], acc[mi][3][3]);
        dst[0]  = u0;
        dst[32] = u1;
    }
}

// ---------- K2: recurrence, 64 CTAs (pair x rank), col-split exchange --------------
__global__ void __launch_bounds__(512, 1)
rnn_k2(float* __restrict__ out) {
    __shared__ unsigned apack[2 * 1024];     // own-K A-frags, double-buffered (8KB)
    __shared__ uint4    zq[3 * 256];         // fp16 Z stream, triple-buffered (12KB)
    __shared__ float4   pred[512];           // K-half partials (8KB)

    const int tid  = threadIdx.x;
    const int w    = tid >> 5, lane = tid & 31;
    const int g    = lane >> 2, tig = lane & 3;
    const int cg   = w & 7;                  // colgroup: local cols [16cg,16cg+16)
    const int kbh  = w >> 3;                 // K-half: global kits [8*kbh, 8*kbh+8)
    const int pair = blockIdx.x >> 1;
    const int rank = blockIdx.x & 1;
    const bool localA = (kbh == rank);       // own-K half uses smem A-frags
    const int b0r  = pair * 16;
    const int colb = rank * 128;

    for (int i = tid; i < 2048; i += 512) apack[i] = 0u;     // h_{-1}=0 (own half)

    // prefetch Z(0): this CTA's 4KB slice, contiguous
    if (tid < 256)
        cp_async16(&zq[tid], g_ZP + (size_t)(pair * S_LEN) * 512 + rank * 256 + tid);
    CP_COMMIT();

    // weight ring: this warp's 8 kits of colgroup (rank*8+cg), depth-4
    const uint4* Bt = g_WhP16 + ((rank * 8 + cg) * 512 + kbh * 256) + lane;  // += WT4/t
    uint4 pf[PFD];
#pragma unroll
    for (int d = 0; d < PFD; d++) pf[d] = Bt[d * 32];

    // exchange pointers
    const int peerbase = (pair * 2 + (1 - rank)) * 513;
    const int ownbase  = (pair * 2 + rank) * 513;

    int cb = 0;
    for (int t = 0; t < S_LEN; t++) {
        const int nb = (cb + 1 == 3) ? 0 : cb + 1;
        const bool notlast = (t + 1 < S_LEN);
        const int ab = t & 1;

        if (notlast && tid < 256)
            cp_async16(&zq[nb * 256 + tid],
                       g_ZP + (size_t)(pair * S_LEN + t + 1) * 512 + rank * 256 + tid);
        CP_COMMIT();
        CP_WAIT1();          // Z(t) landed
        __syncthreads();     // Z(t) + apack[ab] (epilogue t-1) visible

        // seed: kbh==1 warps carry Z(t); kbh==0 warps start at 0
        float acc[2][4];
        if (kbh == 1) {
            uint4 z = zq[cb * 256 + cg * 32 + lane];
            const __half2* zh = reinterpret_cast<const __half2*>(&z);
            float2 a0 = __half22float2(zh[0]), a1 = __half22float2(zh[1]);
            float2 a2 = __half22float2(zh[2]), a3 = __half22float2(zh[3]);
            acc[0][0] = a0.x; acc[0][1] = a0.y; acc[0][2] = a1.x; acc[0][3] = a1.y;
            acc[1][0] = a2.x; acc[1][1] = a2.y; acc[1][2] = a3.x; acc[1][3] = a3.y;
        } else {
#pragma unroll
            for (int nt = 0; nt < 2; nt++)
#pragma unroll
                for (int j = 0; j < 4; j++) acc[nt][j] = 0.f;
        }

        // GEMM: 8 kits x (A frag + ring W LDG.128 + 2 MMA)
        if (localA) {
            const unsigned* Acb = apack + ab * 1024;
#pragma unroll
            for (int i = 0; i < 8; i++) {
                uint4 p = pf[i & (PFD - 1)];
                const int nk = i + PFD;
                if (nk < 8)            pf[i & (PFD - 1)] = Bt[nk * 32];
                else if (notlast)      pf[i & (PFD - 1)] = Bt[WT4 + (nk - 8) * 32];
                uint4 a = *reinterpret_cast<const uint4*>(&Acb[i * 128 + lane * 4]);
                mma_f16(acc[0], a.x, a.y, a.z, a.w, p.x, p.y);
                mma_f16(acc[1], a.x, a.y, a.z, a.w, p.z, p.w);
            }
        } else {
            // peer half: acquire-poll flag (t>0), then stream A-frags from gmem
            if (t > 0) {
                while (ld_acq(&g_flag[peerbase + t]) == 0)
                    __nanosleep(64);
            }
            const uint4* Ar = g_HX + (size_t)(peerbase + t) * 256 + lane;
            uint4 af[4];
#pragma unroll
            for (int d = 0; d < 4; d++) af[d] = Ar[d * 32];
#pragma unroll
            for (int i = 0; i < 8; i++) {
                uint4 p = pf[i & (PFD - 1)];
                const int nk = i + PFD;
                if (nk < 8)            pf[i & (PFD - 1)] = Bt[nk * 32];
                else if (notlast)      pf[i & (PFD - 1)] = Bt[WT4 + (nk - 8) * 32];
                uint4 a = af[i & 3];
                if (i + 4 < 8) af[i & 3] = Ar[(i + 4) * 32];
                mma_f16(acc[0], a.x, a.y, a.z, a.w, p.x, p.y);
                mma_f16(acc[1], a.x, a.y, a.z, a.w, p.z, p.w);
            }
        }

        // K-half 1 publishes fp32 partials (incl. Z seed)
        if (kbh == 1) {
            pred[(cg * 2 + 0) * 32 + lane] =
                make_float4(acc[0][0], acc[0][1], acc[0][2], acc[0][3]);
            pred[(cg * 2 + 1) * 32 + lane] =
                make_float4(acc[1][0], acc[1][1], acc[1][2], acc[1][3]);
        }
        __syncthreads();     // partials visible; apack[ab] reads of step t done

        // K-half 0: reduce, tanh, write out + own A-frags (smem + exchange + flag)
        if (kbh == 0) {
#pragma unroll
            for (int nt = 0; nt < 2; nt++) {
                float4 p = pred[(cg * 2 + nt) * 32 + lane];
                acc[nt][0] += p.x; acc[nt][1] += p.y;
                acc[nt][2] += p.z; acc[nt][3] += p.w;
            }
            float tv[2][4];
#pragma unroll
            for (int nt = 0; nt < 2; nt++)
#pragma unroll
                for (int j = 0; j < 4; j++)
                    tv[nt][j] = fast_tanh(acc[nt][j]);

#pragma unroll
            for (int half = 0; half < 2; half++) {
                int r = b0r + g + half * 8;
                size_t base = ((size_t)r * S_LEN + t) * DIM + colb;
#pragma unroll
                for (int nt = 0; nt < 2; nt++) {
                    int col = cg * 16 + nt * 8 + tig * 2;
                    *reinterpret_cast<float2*>(out + base + col) =
                        make_float2(tv[nt][half * 2], tv[nt][half * 2 + 1]);
                }
            }

            // A-frag (mma register order) for global kit rank*8+cg
            uint4 u;
            u.x = pack2h(tv[0][0], tv[0][1]);    // j0: row g,   k-lo
            u.y = pack2h(tv[0][2], tv[0][3]);    // j1: row g+8, k-lo
            u.z = pack2h(tv[1][0], tv[1][1]);    // j2: row g,   k-hi
            u.w = pack2h(tv[1][2], tv[1][3]);    // j3: row g+8, k-hi
            *reinterpret_cast<uint4*>(&apack[(ab ^ 1) * 1024 + cg * 128 + lane * 4]) = u;
            g_HX[(size_t)(ownbase + t + 1) * 256 + cg * 32 + lane] = u;

            __threadfence();                       // data visible gpu-wide
            asm volatile("bar.sync 1, 256;" ::: "memory");   // all K-half-0 STGs done
            if (tid == 0) st_rel(&g_flag[ownbase + t + 1], 1u);
        }

        Bt += WT4;
        cb = nb;
    }
}

extern "C" void kernel_launch(void* const* d_in, const int* in_sizes, int n_in,
                              void* d_out, int out_size) {
    const float* x  = (const float*)d_in[0];   // [512,512,256]
    const float* Wx = (const float*)d_in[1];   // [512,256,256]
    const float* Wh = (const float*)d_in[2];   // [512,256,256]
    float* out = (float*)d_out;                // [512,512,256]

    uint4* wxp; cudaGetSymbolAddress((void**)&wxp, g_WxP4);
    uint4* whp; cudaGetSymbolAddress((void**)&whp, g_WhP16);
    uint4* zp;  cudaGetSymbolAddress((void**)&zp,  g_ZP);
    void* flg;  cudaGetSymbolAddress(&flg, g_flag);

    cudaMemsetAsync(flg, 0, 64 * 513 * sizeof(unsigned));   // reset publish flags

    pack_wx<<<16384, 256>>>(Wx, wxp);
    pack_wh<<<16384, 256>>>(Wh, whp);

    dim3 g1(B_SZ / TM1, S_LEN);                // 16 x 512 CTAs
    rnn_k1<<<g1, 256>>>(x, zp);                // Z (fp16, K2 thread order)
    rnn_k2<<<64, 512>>>(out);                  // 32 pairs x 2 ranks
}